// round 8
// baseline (speedup 1.0000x reference)
#include <cuda_runtime.h>
#include <cuda_fp16.h>
#include <math.h>

// Fixed shapes: features [16,512,768] f32, labels [16,512] i32. N = 8192.
#define H      768
#define H4     (H / 4)          // 192 float4 per row
#define NCLS   10
#define TPB    256
#define NBLK   512              // producer blocks, all co-resident
#define RPB    16               // rows per block (N = NBLK*RPB = 8192)
#define RPW    2                // rows per warp in phase A
#define CH     (NCLS * H)       // 7680 floats
#define CH2    (CH / 2)         // 3840 half2 per partial
#define CH8    (CH / 8)         // 960 uint4 (8 halves) per partial
#define NSLICE (CH2 / TPB)      // 15
#define GRP    8                // producer blocks per reduce group
#define NGRPS  (NBLK / GRP)     // 64 groups
#define QWORK  (CH8 / 4)        // 240 uint4 per reducer quarter
#define NREDB  (NGRPS * 4)      // 256 reducer blocks (even bids)
#define TEMPERATURE 0.07f
#define EPS    1e-12f

// Device scratch. All counters/accumulators zero at load; restored to zero by
// the last reducer block every run (self-cleaning for graph replay).
__device__ __half2  g_part[NBLK * CH2];   // fp16 per-block class sums (7.9 MB)
__device__ float    g_cs  [CH];
__device__ int      g_cnt_tot[NCLS];
__device__ unsigned g_grp_cnt[NGRPS];
__device__ unsigned g_done = 0;

__global__ __launch_bounds__(TPB, 4) void supcon_one(
    const float* __restrict__ feat,
    const int*   __restrict__ labels,
    float*       __restrict__ out,
    int out_size, int N)
{
    __shared__ float acc[CH];        // 30720 B
    __shared__ float inv[RPB];
    __shared__ int   labs[RPB];
    __shared__ unsigned ticket_sh;
    __shared__ float sredA[8];
    __shared__ float sredP[8];
    __shared__ float loss_sh;

    const int tid  = threadIdx.x;
    const int lane = tid & 31;
    const int warp = tid >> 5;
    const int bid  = blockIdx.x;
    const int row0 = bid * RPB;

    // Zero class accumulators.
    for (int i = tid; i < CH; i += TPB) acc[i] = 0.0f;

    // Labels for this block's 16 rows (clamped; consumed after the sync).
    if (tid < RPB) {
        int l = labels[row0 + tid];
        labs[tid] = min(max(l, 0), NCLS - 1);
    }

    // ---- Phase A: each warp computes norms of its 2 rows (warp-only) ----
    #pragma unroll
    for (int rr = 0; rr < RPW; ++rr) {
        const int r = warp * RPW + rr;
        const float4* x4 = reinterpret_cast<const float4*>(
                               feat + (size_t)(row0 + r) * H);
        float4 v[6];
        #pragma unroll
        for (int j = 0; j < 6; ++j)          // 6 independent LDG.128
            v[j] = x4[j * 32 + lane];
        float ss = 0.0f;
        #pragma unroll
        for (int j = 0; j < 6; ++j)
            ss += v[j].x*v[j].x + v[j].y*v[j].y + v[j].z*v[j].z + v[j].w*v[j].w;
        #pragma unroll
        for (int o = 16; o > 0; o >>= 1)
            ss += __shfl_xor_sync(0xffffffffu, ss, o);
        if (lane == 0)
            inv[r] = 1.0f / fmaxf(sqrtf(ss), EPS);
    }
    __syncthreads();

    // ---- Phase B: owner-float4 accumulation (reads hit L2, no barriers) ----
    if (tid < H4) {
        float4* ap = reinterpret_cast<float4*>(acc);
        #pragma unroll
        for (int r0 = 0; r0 < RPB; r0 += 4) {
            float4 v[4];
            #pragma unroll
            for (int j = 0; j < 4; ++j)
                v[j] = reinterpret_cast<const float4*>(
                           feat + (size_t)(row0 + r0 + j) * H)[tid];
            #pragma unroll
            for (int j = 0; j < 4; ++j) {
                const float iv = inv[r0 + j];
                float4* a = ap + labs[r0 + j] * H4 + tid;
                float4 t = *a;
                t.x += v[j].x * iv;
                t.y += v[j].y * iv;
                t.z += v[j].z * iv;
                t.w += v[j].w * iv;
                *a = t;
            }
        }
    }
    __syncthreads();

    // ---- Flush fp16 partials + class counts, then group-arrive ----
    {
        __half2* dst = g_part + (size_t)bid * CH2;
        #pragma unroll
        for (int k = 0; k < NSLICE; ++k) {
            const int i = k * TPB + tid;
            dst[i] = __floats2half2_rn(acc[2 * i], acc[2 * i + 1]);
        }
        if (tid < NCLS) {
            int c = 0;
            #pragma unroll
            for (int r = 0; r < RPB; ++r) c += (labs[r] == tid);
            if (c > 0) atomicAdd(&g_cnt_tot[tid], c);
        }
    }
    __threadfence();   // release partial stores + count atomics
    __syncthreads();
    if (tid == 0) atomicAdd(&g_grp_cnt[bid >> 3], 1u);

    // Odd blocks are producers only.
    if (bid & 1) return;

    // ================= Reduce role (even blocks) ============================
    // Block bid reduces quarter q of group g as soon as its 8 producers arrive.
    const int g = bid >> 3;
    const int q = (bid & 7) >> 1;

    if (tid == 0) {
        volatile unsigned* p = &g_grp_cnt[g];
        while (*p < GRP) __nanosleep(32);
    }
    __syncthreads();
    __threadfence();   // acquire partials

    if (tid < QWORK) {
        const int i4 = q * QWORK + tid;                 // uint4 index [0,960)
        const uint4* base = reinterpret_cast<const uint4*>(g_part)
                            + (size_t)g * GRP * CH8 + i4;
        float s[8] = {0,0,0,0,0,0,0,0};
        #pragma unroll
        for (int b = 0; b < GRP; ++b) {                 // 8 independent LDG.128
            uint4 u = base[(size_t)b * CH8];
            float2 f0 = __half22float2(*reinterpret_cast<__half2*>(&u.x));
            float2 f1 = __half22float2(*reinterpret_cast<__half2*>(&u.y));
            float2 f2 = __half22float2(*reinterpret_cast<__half2*>(&u.z));
            float2 f3 = __half22float2(*reinterpret_cast<__half2*>(&u.w));
            s[0] += f0.x; s[1] += f0.y; s[2] += f1.x; s[3] += f1.y;
            s[4] += f2.x; s[5] += f2.y; s[6] += f3.x; s[7] += f3.y;
        }
        #pragma unroll
        for (int k = 0; k < 8; ++k)
            atomicAdd(&g_cs[8 * i4 + k], s[k]);
    }

    // Last-reducer ticket.
    __threadfence();
    __syncthreads();
    if (tid == 0) ticket_sh = atomicAdd(&g_done, 1u);
    __syncthreads();
    if (ticket_sh != NREDB - 1) return;
    __threadfence();   // acquire all g_cs adds

    // ================= Epilogue (f32, last block) ===========================
    float p_all = 0.0f, p_pos = 0.0f;
    #pragma unroll
    for (int k = 0; k < H / TPB; ++k) {
        const int h = k * TPB + tid;
        float sh = 0.0f;
        #pragma unroll
        for (int c = 0; c < NCLS; ++c) {
            float vv = g_cs[c * H + h];
            sh    += vv;
            p_pos += vv * vv;
        }
        p_all += sh * sh;
    }
    #pragma unroll
    for (int o = 16; o > 0; o >>= 1) {
        p_all += __shfl_xor_sync(0xffffffffu, p_all, o);
        p_pos += __shfl_xor_sync(0xffffffffu, p_pos, o);
    }
    if (lane == 0) { sredA[warp] = p_all; sredP[warp] = p_pos; }
    __syncthreads();

    if (tid == 0) {
        float A = 0.0f, P = 0.0f;
        #pragma unroll
        for (int w = 0; w < 8; ++w) { A += sredA[w]; P += sredP[w]; }
        float n_pos = 0.0f;
        #pragma unroll
        for (int c = 0; c < NCLS; ++c) {
            float nc = (float)g_cnt_tot[c];
            n_pos += nc * nc;
        }
        float Nf    = (float)N;
        float n_neg = Nf * Nf - n_pos;

        float pos_mean = (P / TEMPERATURE) / n_pos;
        float neg_mean = ((A - P) / TEMPERATURE) / n_neg;
        float d = neg_mean - pos_mean;
        loss_sh = (d > 0.0f) ? d + log1pf(expf(-d)) : log1pf(expf(d));
    }
    __syncthreads();
    for (int i = tid; i < out_size; i += TPB) out[i] = loss_sh;

    // Self-clean all scratch state for the next graph replay.
    for (int i = tid; i < CH; i += TPB) g_cs[i] = 0.0f;
    if (tid < NGRPS) g_grp_cnt[tid] = 0u;
    if (tid < NCLS)  g_cnt_tot[tid] = 0;
    if (tid == 0)    g_done = 0u;
}

// ---------------------------------------------------------------------------
extern "C" void kernel_launch(void* const* d_in, const int* in_sizes, int n_in,
                              void* d_out, int out_size)
{
    const float* feat   = (const float*)d_in[0];
    const int*   labels = (const int*)d_in[1];
    float*       out    = (float*)d_out;
    const int N = in_sizes[1];   // 8192

    supcon_one<<<NBLK, TPB>>>(feat, labels, out, out_size, N);
}